// round 8
// baseline (speedup 1.0000x reference)
#include <cuda_runtime.h>
#include <cstdint>
#include <cstddef>

#define BATCH 512
#define TSEQ  512
#define DDIM  128
#define HDIM  64

// Scratch: encoder final hidden [B,H]; encoder input projections [B*T, 256]
__device__ float g_henc[BATCH * HDIM];
__device__ float g_xp[(size_t)BATCH * TSEQ * 256];

// ---------------- helpers ----------------

__device__ __forceinline__ void fma2(unsigned long long &d, unsigned long long a, unsigned long long b) {
    asm("fma.rn.f32x2 %0, %1, %2, %0;" : "+l"(d) : "l"(a), "l"(b));
}
__device__ __forceinline__ unsigned long long pack2(float lo, float hi) {
    unsigned long long r;
    asm("mov.b64 %0, {%1,%2};" : "=l"(r) : "f"(lo), "f"(hi));
    return r;
}
__device__ __forceinline__ float sum2(unsigned long long v) {
    float lo, hi;
    asm("mov.b64 {%0,%1}, %2;" : "=f"(lo), "=f"(hi) : "l"(v));
    return lo + hi;
}
__device__ __forceinline__ float sigf(float x) {
    return __fdividef(1.0f, 1.0f + __expf(-x));
}
__device__ __forceinline__ float tanh_fast(float x) {
    float ax = fabsf(x);
    float e  = __expf(-2.0f * ax);
    float r  = __fdividef(1.0f - e, 1.0f + e);
    return copysignf(r, x);
}
__device__ __forceinline__ unsigned smaddr(const void* p) {
    unsigned r;
    asm("{ .reg .u64 t; cvta.to.shared.u64 t, %1; cvt.u32.u64 %0, t; }" : "=r"(r) : "l"(p));
    return r;
}
#define CLUSTER_BAR() do { \
    asm volatile("barrier.cluster.arrive.aligned;" ::: "memory"); \
    asm volatile("barrier.cluster.wait.aligned;"   ::: "memory"); } while (0)

__device__ __forceinline__ void mbar_wait_cluster(unsigned addr, unsigned parity) {
    unsigned done;
    asm volatile("{\n\t.reg .pred p;\n\t"
        "mbarrier.try_wait.parity.acquire.cluster.shared::cta.b64 p, [%1], %2;\n\t"
        "selp.b32 %0, 1, 0, p;\n\t}"
        : "=r"(done) : "r"(addr), "r"(parity) : "memory");
    while (!done) {
        asm volatile("{\n\t.reg .pred p;\n\t"
            "mbarrier.try_wait.parity.acquire.cluster.shared::cta.b64 p, [%1], %2, 0x989680;\n\t"
            "selp.b32 %0, 1, 0, p;\n\t}"
            : "=r"(done) : "r"(addr), "r"(parity) : "memory");
    }
}

// =============================================================
// Kernel 1: encoder input projections (time-parallel GEMM)
// g_xp[(b*T+t)*256 + c] = b_e[c] + sum_k x[b,t,k] * Wih_e[c,k]
// Same compute structure as R5, but the output tile is staged in smem
// and stored with one coalesced STG.128 per thread (was: 4 scattered
// STG.32 -> L1TEX sector storm, L1=92.9%).
// =============================================================
__global__ void __launch_bounds__(512, 1)
xp_gemm(const float* __restrict__ x,
        const float* __restrict__ Wih,
        const float* __restrict__ bias)
{
    __shared__ float xs[2][8 * 128];
    __shared__ float Gs[2][8 * 256];
    const int tid = threadIdx.x;
    const int cg = tid >> 2, ks = tid & 3;
    const int c0 = cg, c1 = cg + 128;
    const int b  = blockIdx.x >> 2;
    const int q  = blockIdx.x & 3;

    unsigned long long wa[16], wb[16];
#pragma unroll
    for (int j = 0; j < 8; j++) {
        float4 f = *(const float4*)(Wih + c0 * 128 + 16 * j + 4 * ks);
        wa[2*j] = pack2(f.x, f.y); wa[2*j+1] = pack2(f.z, f.w);
        f = *(const float4*)(Wih + c1 * 128 + 16 * j + 4 * ks);
        wb[2*j] = pack2(f.x, f.y); wb[2*j+1] = pack2(f.z, f.w);
    }
    const float bc0 = bias[c0], bc1 = bias[c1];
    const int r0 = 2 * ks, r1 = r0 + 1;

    const float* xbase = x + ((size_t)b * TSEQ + (size_t)q * 128) * DDIM;
    *(float2*)(&xs[0][tid * 2]) = *(const float2*)(xbase + tid * 2);
    __syncthreads();

    // coalesced store mapping: thread -> float4 of the 8x256 tile
    const int srow = tid >> 6;
    const int scol = (tid & 63) * 4;

    for (int tile = 0; tile < 16; tile++) {
        const int cur = tile & 1, nxt = cur ^ 1;
        float2 pf = make_float2(0.f, 0.f);
        if (tile + 1 < 16)
            pf = *(const float2*)(xbase + (size_t)(tile + 1) * 1024 + tid * 2);

        unsigned long long A0[8], A1[8];
#pragma unroll
        for (int r = 0; r < 8; r++) { A0[r] = 0ull; A1[r] = 0ull; }
#pragma unroll
        for (int j = 0; j < 8; j++) {
#pragma unroll
            for (int r = 0; r < 8; r++) {
                ulonglong2 hv = *(const ulonglong2*)(&xs[cur][r * 128 + 16 * j + 4 * ks]);
                fma2(A0[r], wa[2*j], hv.x); fma2(A0[r], wa[2*j+1], hv.y);
                fma2(A1[r], wb[2*j], hv.x); fma2(A1[r], wb[2*j+1], hv.y);
            }
        }
        float s0[8], s1[8];
#pragma unroll
        for (int r = 0; r < 8; r++) {
            float u = sum2(A0[r]); u += __shfl_xor_sync(~0u, u, 1); u += __shfl_xor_sync(~0u, u, 2); s0[r] = u;
            float v = sum2(A1[r]); v += __shfl_xor_sync(~0u, v, 1); v += __shfl_xor_sync(~0u, v, 2); s1[r] = v;
        }
        float v00 = 0.f, v01 = 0.f, v10 = 0.f, v11 = 0.f;
#pragma unroll
        for (int r = 0; r < 8; r++) {
            if (r == r0) { v00 = s0[r]; v01 = s1[r]; }
            if (r == r1) { v10 = s0[r]; v11 = s1[r]; }
        }
        float* Gt = &Gs[cur][0];
        Gt[r0 * 256 + c0] = v00 + bc0;
        Gt[r0 * 256 + c1] = v01 + bc1;
        Gt[r1 * 256 + c0] = v10 + bc0;
        Gt[r1 * 256 + c1] = v11 + bc1;
        __syncthreads();

        // coalesced STG.128
        {
            float4 v = *(const float4*)(Gt + srow * 256 + scol);
            const size_t row = (size_t)b * TSEQ + (size_t)q * 128 + (size_t)tile * 8 + srow;
            *(float4*)(g_xp + row * 256 + scol) = v;
        }
        if (tile + 1 < 16) *(float2*)(&xs[nxt][tid * 2]) = pf;
        __syncthreads();
    }
}

// =============================================================
// Kernel 2: encoder recurrence. 128 CTAs x 512 thr, 4 batch rows/CTA.
// Thread = (col c = tid>>1, row-half rh = tid&1 -> rows 2rh, 2rh+1),
// full K=64 in registers. No shuffles, direct gate stores.
// xp prefetched straight from L2 into registers by the state threads.
// =============================================================
__global__ void __launch_bounds__(512, 1)
lstm_encoder(const float* __restrict__ Whh)
{
    __shared__ float HB[2 * 4 * 64];      // h double buffer
    __shared__ float G[4 * 260];          // gate pre-activations (padded)
    const int tid = threadIdx.x;
    const int b0  = blockIdx.x * 4;
    const int c   = tid >> 1;
    const int rh  = tid & 1;
    const int ra  = 2 * rh, rb = ra + 1;

    unsigned long long w[32];             // full K=64 weights for col c
#pragma unroll
    for (int j = 0; j < 16; j++) {
        float4 f = *(const float4*)(Whh + c * 64 + 4 * j);
        w[2*j] = pack2(f.x, f.y); w[2*j+1] = pack2(f.z, f.w);
    }

    if (tid < 256) HB[tid] = 0.0f;
    __syncthreads();

    float creg = 0.0f;
    const int sr = tid >> 6, sd = tid & 63;   // state mapping (tid < 256)
    const float* xpb = g_xp + (size_t)(b0 + sr) * TSEQ * 256;

    for (int t = 0; t < TSEQ; t++) {
        const int cur = t & 1, nxt = cur ^ 1;

        // prefetch this step's xp for the state threads (hidden under phase A)
        float xi = 0.f, xf = 0.f, xg = 0.f, xo = 0.f;
        if (tid < 256) {
            const float* xp = xpb + (size_t)t * 256;
            xi = xp[sd]; xf = xp[64 + sd]; xg = xp[128 + sd]; xo = xp[192 + sd];
        }

        // -------- phase A: h @ Whh^T for rows ra, rb --------
        const float* hc = HB + cur * 256;
        unsigned long long a0 = 0ull, a1 = 0ull;
#pragma unroll
        for (int j = 0; j < 16; j++) {
            ulonglong2 h0 = *(const ulonglong2*)(hc + ra * 64 + 4 * j);
            ulonglong2 h1 = *(const ulonglong2*)(hc + rb * 64 + 4 * j);
            fma2(a0, w[2*j], h0.x); fma2(a0, w[2*j+1], h0.y);
            fma2(a1, w[2*j], h1.x); fma2(a1, w[2*j+1], h1.y);
        }
        G[ra * 260 + c] = sum2(a0);
        G[rb * 260 + c] = sum2(a1);
        __syncthreads();

        // -------- phase C --------
        if (tid < 256) {
            float gi = G[sr * 260 +       sd] + xi;
            float gf = G[sr * 260 +  64 + sd] + xf;
            float gg = G[sr * 260 + 128 + sd] + xg;
            float go = G[sr * 260 + 192 + sd] + xo;
            float iv = sigf(gi), fv = sigf(gf), ov = sigf(go);
            creg = fv * creg + iv * tanh_fast(gg);
            float hv = ov * tanh_fast(creg);
            HB[nxt * 256 + sr * 64 + sd] = hv;
            if (t == TSEQ - 1) g_henc[(b0 + sr) * HDIM + sd] = hv;
        }
        __syncthreads();
    }
}

// =============================================================
// Kernel 3: decoder. 64 clusters x 2 CTAs, 512 thr, 8 batch rows/cluster.
// Same compute structure as R5; per-step barrier.cluster (~490 cyc +
// L1 flush) replaced by mbarrier handshake: tid0 fence + remote arrive,
// all threads acquire-wait on the local mbar (~90 cyc).
// =============================================================
__global__ void __launch_bounds__(512, 1) __cluster_dims__(2, 1, 1)
lstm_decoder(const float* __restrict__ Wih,
             const float* __restrict__ Whh,
             const float* __restrict__ bias,
             float* __restrict__ out)
{
    __shared__ float HB[2 * 8 * 128];   // h double buffer (full 128 dims)
    __shared__ float G[8 * 260];        // gates (padded)
    __shared__ float XP[8 * 256];       // input-projection staging
    __shared__ float HS[8 * 64];        // h_enc staging
    __shared__ __align__(8) unsigned long long mbar;
    const int tid = threadIdx.x;
    unsigned rank; asm("mov.u32 %0, %%cluster_ctarank;" : "=r"(rank));
    const int b0 = (blockIdx.x >> 1) * 8;
    const int cg = tid >> 2, ks = tid & 3;
    const int c0 = cg, c1 = cg + 128;
    const int g0 = (c0 >> 6) * 128 + (int)rank * 64 + (c0 & 63);
    const int g1 = (c1 >> 6) * 128 + (int)rank * 64 + (c1 & 63);

    unsigned long long wa[16], wb[16];
#pragma unroll
    for (int j = 0; j < 8; j++) {
        float4 f = *(const float4*)(Whh + g0 * 128 + 16 * j + 4 * ks);
        wa[2*j] = pack2(f.x, f.y); wa[2*j+1] = pack2(f.z, f.w);
        f = *(const float4*)(Whh + g1 * 128 + 16 * j + 4 * ks);
        wb[2*j] = pack2(f.x, f.y); wb[2*j+1] = pack2(f.z, f.w);
    }

    HS[tid] = g_henc[b0 * HDIM + tid];
    HB[tid] = 0.0f; HB[tid + 512] = 0.0f;   // zero buffer 0
    if (tid == 0) {
        unsigned ma = smaddr(&mbar);
        asm volatile("mbarrier.init.shared.b64 [%0], 1;" :: "r"(ma) : "memory");
    }
    __syncthreads();

    // xp[r][c] = b + h_enc[r] . Wih[gr(c)]   (constant over time)
#pragma unroll
    for (int m = 0; m < 4; m++) {
        int idx = m * 512 + tid;
        int r = idx >> 8, c = idx & 255;
        int gr = (c >> 6) * 128 + (int)rank * 64 + (c & 63);
        const float* wv = Wih + gr * 64;
        const float* hv = HS + r * 64;
        float acc = bias[gr];
#pragma unroll
        for (int k = 0; k < 64; k++) acc += wv[k] * hv[k];
        XP[r * 256 + c] = acc;
    }
    __syncthreads();

    const int r0 = 2 * ks, r1 = r0 + 1;
    const float xp00 = XP[r0 * 256 + c0], xp01 = XP[r0 * 256 + c1];
    const float xp10 = XP[r1 * 256 + c0], xp11 = XP[r1 * 256 + c1];

    unsigned hb_peer, mbar_peer;
    {
        unsigned loc = smaddr(HB);
        asm("mapa.shared::cluster.u32 %0, %1, %2;" : "=r"(hb_peer) : "r"(loc), "r"(rank ^ 1u));
        unsigned ma = smaddr(&mbar);
        asm("mapa.shared::cluster.u32 %0, %1, %2;" : "=r"(mbar_peer) : "r"(ma), "r"(rank ^ 1u));
    }
    const unsigned mbar_local = smaddr(&mbar);
    CLUSTER_BAR();   // mbar init + HB zero + XP visible cluster-wide

    float creg = 0.0f;
    const int sr = tid >> 6, sd = tid & 63;
    float* outp = out + (size_t)(b0 + sr) * TSEQ * DDIM + rank * 64 + sd;
    const int hoff = sr * 128 + (int)rank * 64 + sd;

    for (int t = 0; t < TSEQ; t++) {
        const int cur = t & 1, nxt = cur ^ 1;
        const float* hc = HB + cur * 1024;

        // -------- phase A --------
        unsigned long long A0[8], A1[8];
#pragma unroll
        for (int r = 0; r < 8; r++) { A0[r] = 0ull; A1[r] = 0ull; }
#pragma unroll
        for (int j = 0; j < 8; j++) {
#pragma unroll
            for (int r = 0; r < 8; r++) {
                ulonglong2 hv = *(const ulonglong2*)(hc + r * 128 + 16 * j + 4 * ks);
                fma2(A0[r], wa[2*j], hv.x); fma2(A0[r], wa[2*j+1], hv.y);
                fma2(A1[r], wb[2*j], hv.x); fma2(A1[r], wb[2*j+1], hv.y);
            }
        }
        float s0[8], s1[8];
#pragma unroll
        for (int r = 0; r < 8; r++) {
            float u = sum2(A0[r]); u += __shfl_xor_sync(~0u, u, 1); u += __shfl_xor_sync(~0u, u, 2); s0[r] = u;
            float v = sum2(A1[r]); v += __shfl_xor_sync(~0u, v, 1); v += __shfl_xor_sync(~0u, v, 2); s1[r] = v;
        }
        float v00 = 0.f, v01 = 0.f, v10 = 0.f, v11 = 0.f;
#pragma unroll
        for (int r = 0; r < 8; r++) {
            if (r == r0) { v00 = s0[r]; v01 = s1[r]; }
            if (r == r1) { v10 = s0[r]; v11 = s1[r]; }
        }
        G[r0 * 260 + c0] = v00 + xp00;
        G[r0 * 260 + c1] = v01 + xp01;
        G[r1 * 260 + c0] = v10 + xp10;
        G[r1 * 260 + c1] = v11 + xp11;
        __syncthreads();

        // -------- phase C --------
        {
            float gi = G[sr * 260 +       sd];
            float gf = G[sr * 260 +  64 + sd];
            float gg = G[sr * 260 + 128 + sd];
            float go = G[sr * 260 + 192 + sd];
            float iv = sigf(gi), fv = sigf(gf), ov = sigf(go);
            creg = fv * creg + iv * tanh_fast(gg);
            float hv = ov * tanh_fast(creg);
            outp[(size_t)t * DDIM] = hv;
            if (t + 1 < TSEQ) {
                HB[nxt * 1024 + hoff] = hv;
                unsigned pa = hb_peer + (unsigned)((nxt * 1024 + hoff) * 4);
                asm volatile("st.shared::cluster.b32 [%0], %1;" :: "r"(pa), "f"(hv) : "memory");
            }
        }
        // -------- handshake (skip after last step) --------
        if (t + 1 < TSEQ) {
            __syncthreads();   // all local+remote stores of this CTA issued
            if (tid == 0) {
                asm volatile("fence.acq_rel.cluster;" ::: "memory");
                asm volatile("mbarrier.arrive.release.cluster.shared::cluster.b64 _, [%0];"
                             :: "r"(mbar_peer) : "memory");
            }
            mbar_wait_cluster(mbar_local, (unsigned)(t & 1));
        }
    }
}

// =============================================================
// launch
// =============================================================
extern "C" void kernel_launch(void* const* d_in, const int* in_sizes, int n_in,
                              void* d_out, int out_size)
{
    const float* x     = (const float*)d_in[0];
    const float* Wih_e = (const float*)d_in[1];
    const float* Whh_e = (const float*)d_in[2];
    const float* b_e   = (const float*)d_in[3];
    const float* Wih_d = (const float*)d_in[4];
    const float* Whh_d = (const float*)d_in[5];
    const float* b_d   = (const float*)d_in[6];
    float* out = (float*)d_out;

    xp_gemm<<<2048, 512>>>(x, Wih_e, b_e);
    lstm_encoder<<<128, 512>>>(Whh_e);
    lstm_decoder<<<128, 512>>>(Wih_d, Whh_d, b_d, out);
}

// round 10
// speedup vs baseline: 1.1179x; 1.1179x over previous
#include <cuda_runtime.h>
#include <cstdint>
#include <cstddef>

#define BATCH 512
#define TSEQ  512
#define DDIM  128
#define HDIM  64

// Scratch: encoder final hidden [B,H]; encoder input projections [B*T, 256]
__device__ float g_henc[BATCH * HDIM];
__device__ float g_xp[(size_t)BATCH * TSEQ * 256];

// ---------------- helpers ----------------

__device__ __forceinline__ void fma2(unsigned long long &d, unsigned long long a, unsigned long long b) {
    asm("fma.rn.f32x2 %0, %1, %2, %0;" : "+l"(d) : "l"(a), "l"(b));
}
__device__ __forceinline__ unsigned long long pack2(float lo, float hi) {
    unsigned long long r;
    asm("mov.b64 %0, {%1,%2};" : "=l"(r) : "f"(lo), "f"(hi));
    return r;
}
__device__ __forceinline__ float sum2(unsigned long long v) {
    float lo, hi;
    asm("mov.b64 {%0,%1}, %2;" : "=f"(lo), "=f"(hi) : "l"(v));
    return lo + hi;
}
__device__ __forceinline__ float sigf(float x) {
    return __fdividef(1.0f, 1.0f + __expf(-x));
}
__device__ __forceinline__ float tanh_fast(float x) {
    float ax = fabsf(x);
    float e  = __expf(-2.0f * ax);
    float r  = __fdividef(1.0f - e, 1.0f + e);
    return copysignf(r, x);
}
__device__ __forceinline__ unsigned smaddr(const void* p) {
    unsigned r;
    asm("{ .reg .u64 t; cvta.to.shared.u64 t, %1; cvt.u32.u64 %0, t; }" : "=r"(r) : "l"(p));
    return r;
}
#define CLUSTER_BAR() do { \
    asm volatile("barrier.cluster.arrive.aligned;" ::: "memory"); \
    asm volatile("barrier.cluster.wait.aligned;"   ::: "memory"); } while (0)

// =============================================================
// Kernel 1: encoder input projections (time-parallel GEMM)
// g_xp[(b*T+t)*256 + c] = b_e[c] + sum_k x[b,t,k] * Wih_e[c,k]
// Shuffle-free: each thread stores its ks-partials to P[r][c][ks]
// (coalesced, 1 wf), then a reduction pass sums float4 partials
// (contiguous, conflict-free) and does coalesced STG.
// =============================================================
__global__ void __launch_bounds__(512, 1)
xp_gemm(const float* __restrict__ x,
        const float* __restrict__ Wih,
        const float* __restrict__ bias)
{
    __shared__ float xs[2][8 * 128];          // 8KB, double-buffered x tile
    __shared__ float P[8 * 256 * 4];          // 32KB, ks-partials [r][c][ks]
    const int tid = threadIdx.x;
    const int cg = tid >> 2, ks = tid & 3;
    const int c0 = cg, c1 = cg + 128;
    const int b  = blockIdx.x >> 2;
    const int q  = blockIdx.x & 3;

    unsigned long long wa[16], wb[16];
#pragma unroll
    for (int j = 0; j < 8; j++) {
        float4 f = *(const float4*)(Wih + c0 * 128 + 16 * j + 4 * ks);
        wa[2*j] = pack2(f.x, f.y); wa[2*j+1] = pack2(f.z, f.w);
        f = *(const float4*)(Wih + c1 * 128 + 16 * j + 4 * ks);
        wb[2*j] = pack2(f.x, f.y); wb[2*j+1] = pack2(f.z, f.w);
    }

    // reduction-phase mapping: thread -> (row = tid>>6, cols cb+64m)
    const int rrow = tid >> 6;
    const int cb   = tid & 63;
    float bb[4];
#pragma unroll
    for (int m = 0; m < 4; m++) bb[m] = bias[cb + 64 * m];

    const float* xbase = x + ((size_t)b * TSEQ + (size_t)q * 128) * DDIM;
    *(float2*)(&xs[0][tid * 2]) = *(const float2*)(xbase + tid * 2);
    __syncthreads();

    for (int tile = 0; tile < 16; tile++) {
        const int cur = tile & 1, nxt = cur ^ 1;
        float2 pf = make_float2(0.f, 0.f);
        if (tile + 1 < 16)
            pf = *(const float2*)(xbase + (size_t)(tile + 1) * 1024 + tid * 2);

        unsigned long long A0[8], A1[8];
#pragma unroll
        for (int r = 0; r < 8; r++) { A0[r] = 0ull; A1[r] = 0ull; }
#pragma unroll
        for (int j = 0; j < 8; j++) {
#pragma unroll
            for (int r = 0; r < 8; r++) {
                ulonglong2 hv = *(const ulonglong2*)(&xs[cur][r * 128 + 16 * j + 4 * ks]);
                fma2(A0[r], wa[2*j], hv.x); fma2(A0[r], wa[2*j+1], hv.y);
                fma2(A1[r], wb[2*j], hv.x); fma2(A1[r], wb[2*j+1], hv.y);
            }
        }
        // coalesced partial stores: addr = r*1024 + c*4 + ks  (c0*4+ks == tid)
#pragma unroll
        for (int r = 0; r < 8; r++) {
            P[r * 1024 + tid]       = sum2(A0[r]);
            P[r * 1024 + 512 + tid] = sum2(A1[r]);
        }
        __syncthreads();

        // reduce 4 ks-partials per output + bias, coalesced STG
        {
            const size_t grow = (size_t)b * TSEQ + (size_t)q * 128 + (size_t)tile * 8 + rrow;
            float* gout = g_xp + grow * 256;
#pragma unroll
            for (int m = 0; m < 4; m++) {
                const int c = cb + 64 * m;
                float4 p = *(const float4*)(&P[(rrow * 256 + c) * 4]);
                gout[c] = p.x + p.y + p.z + p.w + bb[m];
            }
        }
        if (tile + 1 < 16) *(float2*)(&xs[nxt][tid * 2]) = pf;
        __syncthreads();
    }
}

// =============================================================
// Kernel 2: encoder recurrence (R5 version, known good).
// 128 CTAs x 512 thr, 4 batch rows/CTA. Thread: cg=tid>>1 (1 col),
// ks=tid&1. Whh slice in registers; xp staged via smem double buffer.
// =============================================================
__global__ void __launch_bounds__(512, 1)
lstm_encoder(const float* __restrict__ Whh)
{
    __shared__ float HB[2 * 4 * 64];      // h double buffer
    __shared__ float XPs[2 * 4 * 256];    // xp double buffer
    __shared__ float G[4 * 260];          // gate pre-activations (padded)
    const int tid = threadIdx.x;
    const int b0  = blockIdx.x * 4;
    const int cg  = tid >> 1, ks = tid & 1;

    unsigned long long w[16];
#pragma unroll
    for (int j = 0; j < 8; j++) {
        float4 f = *(const float4*)(Whh + cg * 64 + 8 * j + 4 * ks);
        w[2*j] = pack2(f.x, f.y); w[2*j+1] = pack2(f.z, f.w);
    }

    const int pr = tid >> 7;              // xp staging row 0..3
    const int pc = (tid & 127) * 2;       // xp staging col pair
    const float* xpsrc = g_xp + (size_t)(b0 + pr) * TSEQ * 256 + pc;

    if (tid < 256) HB[tid] = 0.0f;
    *(float2*)(&XPs[pr * 256 + pc]) = *(const float2*)(xpsrc);   // t = 0
    __syncthreads();

    float creg = 0.0f;
    const int sr = tid >> 6, sd = tid & 63;   // state mapping (tid < 256)

    for (int t = 0; t < TSEQ; t++) {
        const int cur = t & 1, nxt = cur ^ 1;
        const int tn = (t + 1 < TSEQ) ? t + 1 : t;
        float2 pf = *(const float2*)(xpsrc + (size_t)tn * 256);

        const float* hc = HB + cur * 256;
        unsigned long long a0 = 0ull, a1 = 0ull, a2 = 0ull, a3 = 0ull;
#pragma unroll
        for (int j = 0; j < 8; j++) {
            ulonglong2 h0 = *(const ulonglong2*)(hc + 0 * 64 + 8 * j + 4 * ks);
            ulonglong2 h1 = *(const ulonglong2*)(hc + 1 * 64 + 8 * j + 4 * ks);
            ulonglong2 h2 = *(const ulonglong2*)(hc + 2 * 64 + 8 * j + 4 * ks);
            ulonglong2 h3 = *(const ulonglong2*)(hc + 3 * 64 + 8 * j + 4 * ks);
            fma2(a0, w[2*j], h0.x); fma2(a0, w[2*j+1], h0.y);
            fma2(a1, w[2*j], h1.x); fma2(a1, w[2*j+1], h1.y);
            fma2(a2, w[2*j], h2.x); fma2(a2, w[2*j+1], h2.y);
            fma2(a3, w[2*j], h3.x); fma2(a3, w[2*j+1], h3.y);
        }
        float s0 = sum2(a0); s0 += __shfl_xor_sync(~0u, s0, 1);
        float s1 = sum2(a1); s1 += __shfl_xor_sync(~0u, s1, 1);
        float s2 = sum2(a2); s2 += __shfl_xor_sync(~0u, s2, 1);
        float s3 = sum2(a3); s3 += __shfl_xor_sync(~0u, s3, 1);
        if (ks == 0) { G[0 * 260 + cg] = s0; G[1 * 260 + cg] = s1; }
        else         { G[2 * 260 + cg] = s2; G[3 * 260 + cg] = s3; }
        __syncthreads();

        if (tid < 256) {
            const float* xp = XPs + cur * 1024 + sr * 256;
            float gi = G[sr * 260 +       sd] + xp[      sd];
            float gf = G[sr * 260 +  64 + sd] + xp[ 64 + sd];
            float gg = G[sr * 260 + 128 + sd] + xp[128 + sd];
            float go = G[sr * 260 + 192 + sd] + xp[192 + sd];
            float iv = sigf(gi), fv = sigf(gf), ov = sigf(go);
            creg = fv * creg + iv * tanh_fast(gg);
            float hv = ov * tanh_fast(creg);
            HB[nxt * 256 + sr * 64 + sd] = hv;
            if (t == TSEQ - 1) g_henc[(b0 + sr) * HDIM + sd] = hv;
        }
        *(float2*)(&XPs[nxt * 1024 + pr * 256 + pc]) = pf;
        __syncthreads();
    }
}

// =============================================================
// Kernel 3: decoder. 64 clusters x 2 CTAs, 512 thr, 8 batch rows/cluster.
// R5 structure (CLUSTER_BAR kept), but shuffle-free: ks-partials stored
// coalesced to P[r][c][ks]; phase C reduces float4 partials.
// =============================================================
__global__ void __launch_bounds__(512, 1) __cluster_dims__(2, 1, 1)
lstm_decoder(const float* __restrict__ Wih,
             const float* __restrict__ Whh,
             const float* __restrict__ bias,
             float* __restrict__ out)
{
    __shared__ float HB[2 * 8 * 128];   // h double buffer (full 128 dims)
    __shared__ float P[8 * 256 * 4];    // 32KB ks-partials [r][c][ks]
    __shared__ float XP[8 * 256];       // input-projection staging
    __shared__ float HS[8 * 64];        // h_enc staging
    const int tid = threadIdx.x;
    unsigned rank; asm("mov.u32 %0, %%cluster_ctarank;" : "=r"(rank));
    const int b0 = (blockIdx.x >> 1) * 8;
    const int cg = tid >> 2, ks = tid & 3;
    const int c0 = cg, c1 = cg + 128;
    const int g0 = (c0 >> 6) * 128 + (int)rank * 64 + (c0 & 63);
    const int g1 = (c1 >> 6) * 128 + (int)rank * 64 + (c1 & 63);

    unsigned long long wa[16], wb[16];
#pragma unroll
    for (int j = 0; j < 8; j++) {
        float4 f = *(const float4*)(Whh + g0 * 128 + 16 * j + 4 * ks);
        wa[2*j] = pack2(f.x, f.y); wa[2*j+1] = pack2(f.z, f.w);
        f = *(const float4*)(Whh + g1 * 128 + 16 * j + 4 * ks);
        wb[2*j] = pack2(f.x, f.y); wb[2*j+1] = pack2(f.z, f.w);
    }

    HS[tid] = g_henc[b0 * HDIM + tid];
    HB[tid] = 0.0f; HB[tid + 512] = 0.0f;   // zero buffer 0
    __syncthreads();

    // xp[r][c] = b + h_enc[r] . Wih[gr(c)]   (constant over time)
#pragma unroll
    for (int m = 0; m < 4; m++) {
        int idx = m * 512 + tid;
        int r = idx >> 8, c = idx & 255;
        int gr = (c >> 6) * 128 + (int)rank * 64 + (c & 63);
        const float* wv = Wih + gr * 64;
        const float* hv = HS + r * 64;
        float acc = bias[gr];
#pragma unroll
        for (int k = 0; k < 64; k++) acc += wv[k] * hv[k];
        XP[r * 256 + c] = acc;
    }
    __syncthreads();

    unsigned hb_peer;
    {
        unsigned loc = smaddr(HB);
        asm("mapa.shared::cluster.u32 %0, %1, %2;" : "=r"(hb_peer) : "r"(loc), "r"(rank ^ 1u));
    }
    CLUSTER_BAR();

    float creg = 0.0f;
    const int sr = tid >> 6, sd = tid & 63;
    float* outp = out + (size_t)(b0 + sr) * TSEQ * DDIM + rank * 64 + sd;
    const int hoff = sr * 128 + (int)rank * 64 + sd;

    for (int t = 0; t < TSEQ; t++) {
        const int cur = t & 1, nxt = cur ^ 1;
        const float* hc = HB + cur * 1024;

        // -------- phase A --------
        unsigned long long A0[8], A1[8];
#pragma unroll
        for (int r = 0; r < 8; r++) { A0[r] = 0ull; A1[r] = 0ull; }
#pragma unroll
        for (int j = 0; j < 8; j++) {
#pragma unroll
            for (int r = 0; r < 8; r++) {
                ulonglong2 hv = *(const ulonglong2*)(hc + r * 128 + 16 * j + 4 * ks);
                fma2(A0[r], wa[2*j], hv.x); fma2(A0[r], wa[2*j+1], hv.y);
                fma2(A1[r], wb[2*j], hv.x); fma2(A1[r], wb[2*j+1], hv.y);
            }
        }
        // coalesced partial stores (c0*4+ks == tid; c1*4+ks == tid+512)
#pragma unroll
        for (int r = 0; r < 8; r++) {
            P[r * 1024 + tid]       = sum2(A0[r]);
            P[r * 1024 + 512 + tid] = sum2(A1[r]);
        }
        __syncthreads();

        // -------- phase C: reduce partials + nonlinearity + publish --------
        {
            float4 pi = *(const float4*)(&P[(sr * 256 +       sd) * 4]);
            float4 pf = *(const float4*)(&P[(sr * 256 +  64 + sd) * 4]);
            float4 pg = *(const float4*)(&P[(sr * 256 + 128 + sd) * 4]);
            float4 po = *(const float4*)(&P[(sr * 256 + 192 + sd) * 4]);
            const float* xpr = XP + sr * 256;
            float gi = pi.x + pi.y + pi.z + pi.w + xpr[      sd];
            float gf = pf.x + pf.y + pf.z + pf.w + xpr[ 64 + sd];
            float gg = pg.x + pg.y + pg.z + pg.w + xpr[128 + sd];
            float go = po.x + po.y + po.z + po.w + xpr[192 + sd];
            float iv = sigf(gi), fv = sigf(gf), ov = sigf(go);
            creg = fv * creg + iv * tanh_fast(gg);
            float hv = ov * tanh_fast(creg);
            HB[nxt * 1024 + hoff] = hv;
            unsigned pa = hb_peer + (unsigned)((nxt * 1024 + hoff) * 4);
            asm volatile("st.shared::cluster.b32 [%0], %1;" :: "r"(pa), "f"(hv) : "memory");
            outp[(size_t)t * DDIM] = hv;
        }
        CLUSTER_BAR();
    }
}

// =============================================================
// launch
// =============================================================
extern "C" void kernel_launch(void* const* d_in, const int* in_sizes, int n_in,
                              void* d_out, int out_size)
{
    const float* x     = (const float*)d_in[0];
    const float* Wih_e = (const float*)d_in[1];
    const float* Whh_e = (const float*)d_in[2];
    const float* b_e   = (const float*)d_in[3];
    const float* Wih_d = (const float*)d_in[4];
    const float* Whh_d = (const float*)d_in[5];
    const float* b_d   = (const float*)d_in[6];
    float* out = (float*)d_out;

    xp_gemm<<<2048, 512>>>(x, Wih_e, b_e);
    lstm_encoder<<<128, 512>>>(Whh_e);
    lstm_decoder<<<128, 512>>>(Wih_d, Whh_d, b_d, out);
}

// round 11
// speedup vs baseline: 1.1183x; 1.0004x over previous
#include <cuda_runtime.h>
#include <cstdint>
#include <cstddef>

#define BATCH 512
#define TSEQ  512
#define DDIM  128
#define HDIM  64

// Scratch: encoder final hidden [B,H]; encoder input projections [B*T, 256]
__device__ float g_henc[BATCH * HDIM];
__device__ float g_xp[(size_t)BATCH * TSEQ * 256];

// ---------------- helpers ----------------

__device__ __forceinline__ void fma2(unsigned long long &d, unsigned long long a, unsigned long long b) {
    asm("fma.rn.f32x2 %0, %1, %2, %0;" : "+l"(d) : "l"(a), "l"(b));
}
__device__ __forceinline__ unsigned long long pack2(float lo, float hi) {
    unsigned long long r;
    asm("mov.b64 %0, {%1,%2};" : "=l"(r) : "f"(lo), "f"(hi));
    return r;
}
__device__ __forceinline__ float sum2(unsigned long long v) {
    float lo, hi;
    asm("mov.b64 {%0,%1}, %2;" : "=f"(lo), "=f"(hi) : "l"(v));
    return lo + hi;
}
__device__ __forceinline__ float sigf(float x) {
    return __fdividef(1.0f, 1.0f + __expf(-x));
}
__device__ __forceinline__ float tanh_fast(float x) {
    float ax = fabsf(x);
    float e  = __expf(-2.0f * ax);
    float r  = __fdividef(1.0f - e, 1.0f + e);
    return copysignf(r, x);
}
__device__ __forceinline__ unsigned smaddr(const void* p) {
    unsigned r;
    asm("{ .reg .u64 t; cvta.to.shared.u64 t, %1; cvt.u32.u64 %0, t; }" : "=r"(r) : "l"(p));
    return r;
}
#define CLUSTER_BAR() do { \
    asm volatile("barrier.cluster.arrive.aligned;" ::: "memory"); \
    asm volatile("barrier.cluster.wait.aligned;"   ::: "memory"); } while (0)

// =============================================================
// Kernel 1: encoder input projections (time-parallel GEMM)
// g_xp[(b*T+t)*256 + c] = b_e[c] + sum_k x[b,t,k] * Wih_e[c,k]
// Shuffle-free: each thread stores its ks-partials to P[r][c][ks]
// (coalesced, 1 wf), then a reduction pass sums float4 partials
// (contiguous, conflict-free) and does coalesced STG.
// =============================================================
__global__ void __launch_bounds__(512, 1)
xp_gemm(const float* __restrict__ x,
        const float* __restrict__ Wih,
        const float* __restrict__ bias)
{
    __shared__ float xs[2][8 * 128];          // 8KB, double-buffered x tile
    __shared__ float P[8 * 256 * 4];          // 32KB, ks-partials [r][c][ks]
    const int tid = threadIdx.x;
    const int cg = tid >> 2, ks = tid & 3;
    const int c0 = cg, c1 = cg + 128;
    const int b  = blockIdx.x >> 2;
    const int q  = blockIdx.x & 3;

    unsigned long long wa[16], wb[16];
#pragma unroll
    for (int j = 0; j < 8; j++) {
        float4 f = *(const float4*)(Wih + c0 * 128 + 16 * j + 4 * ks);
        wa[2*j] = pack2(f.x, f.y); wa[2*j+1] = pack2(f.z, f.w);
        f = *(const float4*)(Wih + c1 * 128 + 16 * j + 4 * ks);
        wb[2*j] = pack2(f.x, f.y); wb[2*j+1] = pack2(f.z, f.w);
    }

    // reduction-phase mapping: thread -> (row = tid>>6, cols cb+64m)
    const int rrow = tid >> 6;
    const int cb   = tid & 63;
    float bb[4];
#pragma unroll
    for (int m = 0; m < 4; m++) bb[m] = bias[cb + 64 * m];

    const float* xbase = x + ((size_t)b * TSEQ + (size_t)q * 128) * DDIM;
    *(float2*)(&xs[0][tid * 2]) = *(const float2*)(xbase + tid * 2);
    __syncthreads();

    for (int tile = 0; tile < 16; tile++) {
        const int cur = tile & 1, nxt = cur ^ 1;
        float2 pf = make_float2(0.f, 0.f);
        if (tile + 1 < 16)
            pf = *(const float2*)(xbase + (size_t)(tile + 1) * 1024 + tid * 2);

        unsigned long long A0[8], A1[8];
#pragma unroll
        for (int r = 0; r < 8; r++) { A0[r] = 0ull; A1[r] = 0ull; }
#pragma unroll
        for (int j = 0; j < 8; j++) {
#pragma unroll
            for (int r = 0; r < 8; r++) {
                ulonglong2 hv = *(const ulonglong2*)(&xs[cur][r * 128 + 16 * j + 4 * ks]);
                fma2(A0[r], wa[2*j], hv.x); fma2(A0[r], wa[2*j+1], hv.y);
                fma2(A1[r], wb[2*j], hv.x); fma2(A1[r], wb[2*j+1], hv.y);
            }
        }
        // coalesced partial stores: addr = r*1024 + c*4 + ks  (c0*4+ks == tid)
#pragma unroll
        for (int r = 0; r < 8; r++) {
            P[r * 1024 + tid]       = sum2(A0[r]);
            P[r * 1024 + 512 + tid] = sum2(A1[r]);
        }
        __syncthreads();

        // reduce 4 ks-partials per output + bias, coalesced STG
        {
            const size_t grow = (size_t)b * TSEQ + (size_t)q * 128 + (size_t)tile * 8 + rrow;
            float* gout = g_xp + grow * 256;
#pragma unroll
            for (int m = 0; m < 4; m++) {
                const int c = cb + 64 * m;
                float4 p = *(const float4*)(&P[(rrow * 256 + c) * 4]);
                gout[c] = p.x + p.y + p.z + p.w + bb[m];
            }
        }
        if (tile + 1 < 16) *(float2*)(&xs[nxt][tid * 2]) = pf;
        __syncthreads();
    }
}

// =============================================================
// Kernel 2: encoder recurrence (R5 version, known good).
// 128 CTAs x 512 thr, 4 batch rows/CTA. Thread: cg=tid>>1 (1 col),
// ks=tid&1. Whh slice in registers; xp staged via smem double buffer.
// =============================================================
__global__ void __launch_bounds__(512, 1)
lstm_encoder(const float* __restrict__ Whh)
{
    __shared__ float HB[2 * 4 * 64];      // h double buffer
    __shared__ float XPs[2 * 4 * 256];    // xp double buffer
    __shared__ float G[4 * 260];          // gate pre-activations (padded)
    const int tid = threadIdx.x;
    const int b0  = blockIdx.x * 4;
    const int cg  = tid >> 1, ks = tid & 1;

    unsigned long long w[16];
#pragma unroll
    for (int j = 0; j < 8; j++) {
        float4 f = *(const float4*)(Whh + cg * 64 + 8 * j + 4 * ks);
        w[2*j] = pack2(f.x, f.y); w[2*j+1] = pack2(f.z, f.w);
    }

    const int pr = tid >> 7;              // xp staging row 0..3
    const int pc = (tid & 127) * 2;       // xp staging col pair
    const float* xpsrc = g_xp + (size_t)(b0 + pr) * TSEQ * 256 + pc;

    if (tid < 256) HB[tid] = 0.0f;
    *(float2*)(&XPs[pr * 256 + pc]) = *(const float2*)(xpsrc);   // t = 0
    __syncthreads();

    float creg = 0.0f;
    const int sr = tid >> 6, sd = tid & 63;   // state mapping (tid < 256)

    for (int t = 0; t < TSEQ; t++) {
        const int cur = t & 1, nxt = cur ^ 1;
        const int tn = (t + 1 < TSEQ) ? t + 1 : t;
        float2 pf = *(const float2*)(xpsrc + (size_t)tn * 256);

        const float* hc = HB + cur * 256;
        unsigned long long a0 = 0ull, a1 = 0ull, a2 = 0ull, a3 = 0ull;
#pragma unroll
        for (int j = 0; j < 8; j++) {
            ulonglong2 h0 = *(const ulonglong2*)(hc + 0 * 64 + 8 * j + 4 * ks);
            ulonglong2 h1 = *(const ulonglong2*)(hc + 1 * 64 + 8 * j + 4 * ks);
            ulonglong2 h2 = *(const ulonglong2*)(hc + 2 * 64 + 8 * j + 4 * ks);
            ulonglong2 h3 = *(const ulonglong2*)(hc + 3 * 64 + 8 * j + 4 * ks);
            fma2(a0, w[2*j], h0.x); fma2(a0, w[2*j+1], h0.y);
            fma2(a1, w[2*j], h1.x); fma2(a1, w[2*j+1], h1.y);
            fma2(a2, w[2*j], h2.x); fma2(a2, w[2*j+1], h2.y);
            fma2(a3, w[2*j], h3.x); fma2(a3, w[2*j+1], h3.y);
        }
        float s0 = sum2(a0); s0 += __shfl_xor_sync(~0u, s0, 1);
        float s1 = sum2(a1); s1 += __shfl_xor_sync(~0u, s1, 1);
        float s2 = sum2(a2); s2 += __shfl_xor_sync(~0u, s2, 1);
        float s3 = sum2(a3); s3 += __shfl_xor_sync(~0u, s3, 1);
        if (ks == 0) { G[0 * 260 + cg] = s0; G[1 * 260 + cg] = s1; }
        else         { G[2 * 260 + cg] = s2; G[3 * 260 + cg] = s3; }
        __syncthreads();

        if (tid < 256) {
            const float* xp = XPs + cur * 1024 + sr * 256;
            float gi = G[sr * 260 +       sd] + xp[      sd];
            float gf = G[sr * 260 +  64 + sd] + xp[ 64 + sd];
            float gg = G[sr * 260 + 128 + sd] + xp[128 + sd];
            float go = G[sr * 260 + 192 + sd] + xp[192 + sd];
            float iv = sigf(gi), fv = sigf(gf), ov = sigf(go);
            creg = fv * creg + iv * tanh_fast(gg);
            float hv = ov * tanh_fast(creg);
            HB[nxt * 256 + sr * 64 + sd] = hv;
            if (t == TSEQ - 1) g_henc[(b0 + sr) * HDIM + sd] = hv;
        }
        *(float2*)(&XPs[nxt * 1024 + pr * 256 + pc]) = pf;
        __syncthreads();
    }
}

// =============================================================
// Kernel 3: decoder. 64 clusters x 2 CTAs, 512 thr, 8 batch rows/cluster.
// R5 structure (CLUSTER_BAR kept), but shuffle-free: ks-partials stored
// coalesced to P[r][c][ks]; phase C reduces float4 partials.
// =============================================================
__global__ void __launch_bounds__(512, 1) __cluster_dims__(2, 1, 1)
lstm_decoder(const float* __restrict__ Wih,
             const float* __restrict__ Whh,
             const float* __restrict__ bias,
             float* __restrict__ out)
{
    __shared__ float HB[2 * 8 * 128];   // h double buffer (full 128 dims)
    __shared__ float P[8 * 256 * 4];    // 32KB ks-partials [r][c][ks]
    __shared__ float XP[8 * 256];       // input-projection staging
    __shared__ float HS[8 * 64];        // h_enc staging
    const int tid = threadIdx.x;
    unsigned rank; asm("mov.u32 %0, %%cluster_ctarank;" : "=r"(rank));
    const int b0 = (blockIdx.x >> 1) * 8;
    const int cg = tid >> 2, ks = tid & 3;
    const int c0 = cg, c1 = cg + 128;
    const int g0 = (c0 >> 6) * 128 + (int)rank * 64 + (c0 & 63);
    const int g1 = (c1 >> 6) * 128 + (int)rank * 64 + (c1 & 63);

    unsigned long long wa[16], wb[16];
#pragma unroll
    for (int j = 0; j < 8; j++) {
        float4 f = *(const float4*)(Whh + g0 * 128 + 16 * j + 4 * ks);
        wa[2*j] = pack2(f.x, f.y); wa[2*j+1] = pack2(f.z, f.w);
        f = *(const float4*)(Whh + g1 * 128 + 16 * j + 4 * ks);
        wb[2*j] = pack2(f.x, f.y); wb[2*j+1] = pack2(f.z, f.w);
    }

    HS[tid] = g_henc[b0 * HDIM + tid];
    HB[tid] = 0.0f; HB[tid + 512] = 0.0f;   // zero buffer 0
    __syncthreads();

    // xp[r][c] = b + h_enc[r] . Wih[gr(c)]   (constant over time)
#pragma unroll
    for (int m = 0; m < 4; m++) {
        int idx = m * 512 + tid;
        int r = idx >> 8, c = idx & 255;
        int gr = (c >> 6) * 128 + (int)rank * 64 + (c & 63);
        const float* wv = Wih + gr * 64;
        const float* hv = HS + r * 64;
        float acc = bias[gr];
#pragma unroll
        for (int k = 0; k < 64; k++) acc += wv[k] * hv[k];
        XP[r * 256 + c] = acc;
    }
    __syncthreads();

    unsigned hb_peer;
    {
        unsigned loc = smaddr(HB);
        asm("mapa.shared::cluster.u32 %0, %1, %2;" : "=r"(hb_peer) : "r"(loc), "r"(rank ^ 1u));
    }
    CLUSTER_BAR();

    float creg = 0.0f;
    const int sr = tid >> 6, sd = tid & 63;
    float* outp = out + (size_t)(b0 + sr) * TSEQ * DDIM + rank * 64 + sd;
    const int hoff = sr * 128 + (int)rank * 64 + sd;

    for (int t = 0; t < TSEQ; t++) {
        const int cur = t & 1, nxt = cur ^ 1;
        const float* hc = HB + cur * 1024;

        // -------- phase A --------
        unsigned long long A0[8], A1[8];
#pragma unroll
        for (int r = 0; r < 8; r++) { A0[r] = 0ull; A1[r] = 0ull; }
#pragma unroll
        for (int j = 0; j < 8; j++) {
#pragma unroll
            for (int r = 0; r < 8; r++) {
                ulonglong2 hv = *(const ulonglong2*)(hc + r * 128 + 16 * j + 4 * ks);
                fma2(A0[r], wa[2*j], hv.x); fma2(A0[r], wa[2*j+1], hv.y);
                fma2(A1[r], wb[2*j], hv.x); fma2(A1[r], wb[2*j+1], hv.y);
            }
        }
        // coalesced partial stores (c0*4+ks == tid; c1*4+ks == tid+512)
#pragma unroll
        for (int r = 0; r < 8; r++) {
            P[r * 1024 + tid]       = sum2(A0[r]);
            P[r * 1024 + 512 + tid] = sum2(A1[r]);
        }
        __syncthreads();

        // -------- phase C: reduce partials + nonlinearity + publish --------
        {
            float4 pi = *(const float4*)(&P[(sr * 256 +       sd) * 4]);
            float4 pf = *(const float4*)(&P[(sr * 256 +  64 + sd) * 4]);
            float4 pg = *(const float4*)(&P[(sr * 256 + 128 + sd) * 4]);
            float4 po = *(const float4*)(&P[(sr * 256 + 192 + sd) * 4]);
            const float* xpr = XP + sr * 256;
            float gi = pi.x + pi.y + pi.z + pi.w + xpr[      sd];
            float gf = pf.x + pf.y + pf.z + pf.w + xpr[ 64 + sd];
            float gg = pg.x + pg.y + pg.z + pg.w + xpr[128 + sd];
            float go = po.x + po.y + po.z + po.w + xpr[192 + sd];
            float iv = sigf(gi), fv = sigf(gf), ov = sigf(go);
            creg = fv * creg + iv * tanh_fast(gg);
            float hv = ov * tanh_fast(creg);
            HB[nxt * 1024 + hoff] = hv;
            unsigned pa = hb_peer + (unsigned)((nxt * 1024 + hoff) * 4);
            asm volatile("st.shared::cluster.b32 [%0], %1;" :: "r"(pa), "f"(hv) : "memory");
            outp[(size_t)t * DDIM] = hv;
        }
        CLUSTER_BAR();
    }
}

// =============================================================
// launch
// =============================================================
extern "C" void kernel_launch(void* const* d_in, const int* in_sizes, int n_in,
                              void* d_out, int out_size)
{
    const float* x     = (const float*)d_in[0];
    const float* Wih_e = (const float*)d_in[1];
    const float* Whh_e = (const float*)d_in[2];
    const float* b_e   = (const float*)d_in[3];
    const float* Wih_d = (const float*)d_in[4];
    const float* Whh_d = (const float*)d_in[5];
    const float* b_d   = (const float*)d_in[6];
    float* out = (float*)d_out;

    xp_gemm<<<2048, 512>>>(x, Wih_e, b_e);
    lstm_encoder<<<128, 512>>>(Whh_e);
    lstm_decoder<<<128, 512>>>(Wih_d, Whh_d, b_d, out);
}